// round 4
// baseline (speedup 1.0000x reference)
#include <cuda_runtime.h>
#include <cuda_bf16.h>
#include <cstdint>
#include <math.h>

#define NROWS 32768
#define FDIM  128
#define KDIM  64
#define MNBR  32
#define NTILES (NROWS/4)

// Scratch (allocation-free rule: __device__ globals)
__device__ float g_xi [NROWS*FDIM];
__device__ float g_xjp[NROWS*FDIM];
__device__ float g_m0 [NROWS*FDIM];
__device__ float g_m1 [NROWS*FDIM];
__device__ float g_t  [NROWS*FDIM];

__device__ __forceinline__ float sspf(float a) {
    return fmaxf(a, 0.0f) + log1pf(expf(-fabsf(a))) - 0.69314718055994530942f;
}

// ---------------- row GEMM (unchanged, validated @49us each) ----------------
template<bool IN_SSP, bool ADD, bool MULVEC>
__global__ __launch_bounds__(128, 3) void rowgemm(
    const float* __restrict__ in, const float* __restrict__ W,
    const float* __restrict__ bias, const float* __restrict__ addp,
    const float* __restrict__ mulv, float* __restrict__ out)
{
    __shared__ float xs[8 * FDIM];
    const int f = threadIdx.x;

    float w[FDIM];
    {
        const float4* W4 = (const float4*)(W + f * FDIM);
        #pragma unroll
        for (int i = 0; i < FDIM / 4; i++) {
            float4 v = W4[i];
            w[4*i] = v.x; w[4*i+1] = v.y; w[4*i+2] = v.z; w[4*i+3] = v.w;
        }
    }
    const float bf = bias[f];
    const float mv = MULVEC ? mulv[f] : 1.0f;

    const int ntiles = NROWS / 8;
    for (int tile = blockIdx.x; tile < ntiles; tile += gridDim.x) {
        const int r0 = tile * 8;
        const float4* inp = (const float4*)(in + r0 * FDIM);
        float4* xs4 = (float4*)xs;
        #pragma unroll
        for (int i = 0; i < 2; i++) {
            float4 v = inp[f + 128 * i];
            if (IN_SSP) { v.x = sspf(v.x); v.y = sspf(v.y); v.z = sspf(v.z); v.w = sspf(v.w); }
            xs4[f + 128 * i] = v;
        }
        __syncthreads();
        for (int r = 0; r < 8; r++) {
            const float4* xr = (const float4*)(xs + r * FDIM);
            float a0 = 0.f, a1 = 0.f, a2 = 0.f, a3 = 0.f;
            #pragma unroll
            for (int kk = 0; kk < FDIM / 4; kk++) {
                float4 v = xr[kk];
                a0 += v.x * w[4*kk];   a1 += v.y * w[4*kk+1];
                a2 += v.z * w[4*kk+2]; a3 += v.w * w[4*kk+3];
            }
            float o = bf + ((a0 + a1) + (a2 + a3));
            const int n = r0 + r;
            if (ADD) o += addp[n * FDIM + f] * mv;
            out[n * FDIM + f] = o;
        }
        __syncthreads();
    }
}

// ---------------- mma.sync helpers (baseline PTX, no arch-specific instrs) ----------------
__device__ __forceinline__ uint32_t s2u(const void* p) {
    uint32_t a;
    asm("{ .reg .u64 t; cvta.to.shared.u64 t, %1; cvt.u32.u64 %0, t; }" : "=r"(a) : "l"(p));
    return a;
}

#define LDM_X4(r, addr) \
    asm volatile("ldmatrix.sync.aligned.m8n8.x4.shared.b16 {%0,%1,%2,%3}, [%4];" \
        : "=r"((r)[0]), "=r"((r)[1]), "=r"((r)[2]), "=r"((r)[3]) : "r"(addr))

#define MMA_BF16(d, a, b0, b1) \
    asm volatile("mma.sync.aligned.m16n8k16.row.col.f32.bf16.bf16.f32 " \
        "{%0,%1,%2,%3}, {%4,%5,%6,%7}, {%8,%9}, {%0,%1,%2,%3};" \
        : "+f"((d)[0]), "+f"((d)[1]), "+f"((d)[2]), "+f"((d)[3]) \
        : "r"((a)[0]), "r"((a)[1]), "r"((a)[2]), "r"((a)[3]), "r"(b0), "r"(b1))

// ---------------- smem layout (bytes) ----------------
// bf16 tiles stored [row][72] (pad 8) -> 144 B/row, 16B-aligned rows.
#define OFF_AH   0u
#define OFF_AL   18432u
#define OFF_BH   36864u
#define OFF_BL   55296u
#define OFF_SLAB 73728u     // float[128][132] = 67584 B
#define OFF_XI   141312u    // float[512]
#define OFF_PART 143360u    // float[1024]
#define OFF_ATT  147456u    // float[128]
#define OFF_JIDX 147968u    // int[128]
#define SM_TOTAL 148480u

#define SLAB_STRIDE 132

// ---------------- fused edge-filter GEMM (mma.sync bf16x3) + gather + attention ----------------
__global__ void __launch_bounds__(256) attn_mma(
    const float* __restrict__ rbf, const int* __restrict__ idxj,
    const float* __restrict__ k2f, const float* __restrict__ xi,
    const float* __restrict__ xjp, float* __restrict__ mout)
{
    extern __shared__ char smem[];
    __nv_bfloat16* AH = (__nv_bfloat16*)(smem + OFF_AH);
    __nv_bfloat16* AL = (__nv_bfloat16*)(smem + OFF_AL);
    __nv_bfloat16* BH = (__nv_bfloat16*)(smem + OFF_BH);
    __nv_bfloat16* BL = (__nv_bfloat16*)(smem + OFF_BL);
    float* slab   = (float*)(smem + OFF_SLAB);
    float* xi_sm  = (float*)(smem + OFF_XI);
    float* part   = (float*)(smem + OFF_PART);
    float* att_sm = (float*)(smem + OFF_ATT);
    int*   jidx   = (int*)  (smem + OFF_JIDX);

    const int tid = threadIdx.x;
    const int wid = tid >> 5, lid = tid & 31;
    const uint32_t sb = s2u(smem);

    // B = k2f [128 f x 64 k], hi/lo bf16 split, loaded once
    #pragma unroll
    for (int i = 0; i < 8; i++) {
        int fidx = tid + 256 * i;             // float4 index, 2048 total
        float4 v = ((const float4*)k2f)[fidx];
        int row = fidx >> 4, c = (fidx & 15) * 4;
        __nv_bfloat16 h0 = __float2bfloat16(v.x), h1 = __float2bfloat16(v.y),
                      h2 = __float2bfloat16(v.z), h3 = __float2bfloat16(v.w);
        __nv_bfloat16 l0 = __float2bfloat16(v.x - __bfloat162float(h0)),
                      l1 = __float2bfloat16(v.y - __bfloat162float(h1)),
                      l2 = __float2bfloat16(v.z - __bfloat162float(h2)),
                      l3 = __float2bfloat16(v.w - __bfloat162float(h3));
        *(__nv_bfloat162*)(BH + row*72 + c)     = __nv_bfloat162(h0, h1);
        *(__nv_bfloat162*)(BH + row*72 + c + 2) = __nv_bfloat162(h2, h3);
        *(__nv_bfloat162*)(BL + row*72 + c)     = __nv_bfloat162(l0, l1);
        *(__nv_bfloat162*)(BL + row*72 + c + 2) = __nv_bfloat162(l2, l3);
    }
    __syncthreads();

    // per-lane ldmatrix byte offsets
    const uint32_t aL = ((((lid & 7) + (lid & 8)) * 72) + ((lid & 16) ? 8 : 0)) * 2;
    const uint32_t bL = ((((lid & 7) + ((lid & 16) >> 1)) * 72) + ((lid & 8) ? 8 : 0)) * 2;
    const int wr = wid & 3, wc = wid >> 2;

    const int f  = tid & 127;
    const int q  = f >> 5;
    const int e0 = tid >> 7;

    for (int tile = blockIdx.x; tile < NTILES; tile += gridDim.x) {
        const int n0 = tile * 4;

        // A tile: 128 edges x 64 rbf, hi/lo split
        const float4* rp = (const float4*)(rbf + (size_t)tile * 8192);
        #pragma unroll
        for (int i = 0; i < 8; i++) {
            int fidx = tid + 256 * i;
            float4 v = rp[fidx];
            int row = fidx >> 4, c = (fidx & 15) * 4;
            __nv_bfloat16 h0 = __float2bfloat16(v.x), h1 = __float2bfloat16(v.y),
                          h2 = __float2bfloat16(v.z), h3 = __float2bfloat16(v.w);
            __nv_bfloat16 l0 = __float2bfloat16(v.x - __bfloat162float(h0)),
                          l1 = __float2bfloat16(v.y - __bfloat162float(h1)),
                          l2 = __float2bfloat16(v.z - __bfloat162float(h2)),
                          l3 = __float2bfloat16(v.w - __bfloat162float(h3));
            *(__nv_bfloat162*)(AH + row*72 + c)     = __nv_bfloat162(h0, h1);
            *(__nv_bfloat162*)(AH + row*72 + c + 2) = __nv_bfloat162(h2, h3);
            *(__nv_bfloat162*)(AL + row*72 + c)     = __nv_bfloat162(l0, l1);
            *(__nv_bfloat162*)(AL + row*72 + c + 2) = __nv_bfloat162(l2, l3);
        }
        if (tid < 128) jidx[tid] = idxj[tile * 128 + tid];
        #pragma unroll
        for (int i = 0; i < 2; i++) {
            int ix = tid + 256 * i;
            xi_sm[ix] = xi[(size_t)n0 * FDIM + ix];
        }
        __syncthreads();

        // 128x128x64 GEMM: D[e][f] = sum_k A[e][k]*B[f][k], bf16 hi/lo 3-pass
        float acc[2][8][4];
        #pragma unroll
        for (int mt = 0; mt < 2; mt++)
            #pragma unroll
            for (int nb = 0; nb < 8; nb++)
                #pragma unroll
                for (int c = 0; c < 4; c++) acc[mt][nb][c] = 0.f;

        #pragma unroll
        for (int kk = 0; kk < 4; kk++) {
            const uint32_t kb = (uint32_t)kk * 32;   // 16 bf16 = 32 bytes per k-step
            uint32_t ah[2][4], al[2][4], bh[4][4], bl[4][4];
            #pragma unroll
            for (int mt = 0; mt < 2; mt++) {
                uint32_t ro = (uint32_t)(32*wr + 16*mt) * 144 + kb;
                LDM_X4(ah[mt], sb + OFF_AH + aL + ro);
                LDM_X4(al[mt], sb + OFF_AL + aL + ro);
            }
            #pragma unroll
            for (int np = 0; np < 4; np++) {
                uint32_t no = (uint32_t)(64*wc + 16*np) * 144 + kb;
                LDM_X4(bh[np], sb + OFF_BH + bL + no);
                LDM_X4(bl[np], sb + OFF_BL + bL + no);
            }
            #pragma unroll
            for (int mt = 0; mt < 2; mt++)
                #pragma unroll
                for (int np = 0; np < 4; np++) {
                    MMA_BF16(acc[mt][2*np],   ah[mt], bh[np][0], bh[np][1]);
                    MMA_BF16(acc[mt][2*np+1], ah[mt], bh[np][2], bh[np][3]);
                    MMA_BF16(acc[mt][2*np],   ah[mt], bl[np][0], bl[np][1]);
                    MMA_BF16(acc[mt][2*np+1], ah[mt], bl[np][2], bl[np][3]);
                    MMA_BF16(acc[mt][2*np],   al[mt], bh[np][0], bh[np][1]);
                    MMA_BF16(acc[mt][2*np+1], al[mt], bh[np][2], bh[np][3]);
                }
        }

        // fragment -> slab  (lane l: rows g,g+8; cols 2t,2t+1)
        {
            const int g = lid >> 2, t = lid & 3;
            #pragma unroll
            for (int mt = 0; mt < 2; mt++)
                #pragma unroll
                for (int nb = 0; nb < 8; nb++) {
                    int e = 32*wr + 16*mt + g;
                    int c = 64*wc + 8*nb + 2*t;
                    *(float2*)&slab[e * SLAB_STRIDE + c] =
                        make_float2(acc[mt][nb][0], acc[mt][nb][1]);
                    *(float2*)&slab[(e + 8) * SLAB_STRIDE + c] =
                        make_float2(acc[mt][nb][2], acc[mt][nb][3]);
                }
        }
        __syncthreads();

        // product (g * gathered xjp) + logit partials (faithful flat reshape)
        float l0 = 0.f, l1 = 0.f, l2 = 0.f, l3 = 0.f;
        #pragma unroll
        for (int i = 0; i < 64; i++) {
            const int e = 2 * i + e0;
            const int a = e >> 5, m = e & 31;
            float p = slab[e * SLAB_STRIDE + f] * xjp[(size_t)jidx[e] * FDIM + f];
            slab[e * SLAB_STRIDE + f] = p;
            float xv = xi_sm[a * FDIM + 4 * m + q];
            if      (a == 0) l0 += xv * p;
            else if (a == 1) l1 += xv * p;
            else if (a == 2) l2 += xv * p;
            else             l3 += xv * p;
        }
        part[wid * 128 +  0 + lid] = l0;
        part[wid * 128 + 32 + lid] = l1;
        part[wid * 128 + 64 + lid] = l2;
        part[wid * 128 + 96 + lid] = l3;
        __syncthreads();

        if (wid < 4) {
            float lg = 0.f;
            #pragma unroll
            for (int w2 = 0; w2 < 8; w2++) lg += part[w2 * 128 + wid * 32 + lid];
            float mx = lg;
            #pragma unroll
            for (int o = 16; o; o >>= 1) mx = fmaxf(mx, __shfl_xor_sync(0xffffffffu, mx, o));
            float ex = expf(lg - mx);
            float smv = ex;
            #pragma unroll
            for (int o = 16; o; o >>= 1) smv += __shfl_xor_sync(0xffffffffu, smv, o);
            att_sm[wid * 32 + lid] = ex / smv;
        }
        __syncthreads();

        // attention-weighted neighbor sum
        float p0 = 0.f, p1 = 0.f, p2 = 0.f, p3 = 0.f;
        #pragma unroll
        for (int i = 0; i < 64; i++) {
            const int e = 2 * i + e0;
            const int a = e >> 5, m = e & 31;
            float w = att_sm[a * 32 + m];
            float p = slab[e * SLAB_STRIDE + f];
            if      (a == 0) p0 += w * p;
            else if (a == 1) p1 += w * p;
            else if (a == 2) p2 += w * p;
            else             p3 += w * p;
        }
        part[e0 * 512 +   0 + f] = p0;
        part[e0 * 512 + 128 + f] = p1;
        part[e0 * 512 + 256 + f] = p2;
        part[e0 * 512 + 384 + f] = p3;
        __syncthreads();

        #pragma unroll
        for (int i2 = 0; i2 < 2; i2++) {
            int ix = tid + 256 * i2;
            mout[(size_t)n0 * FDIM + ix] = xi_sm[ix] + part[ix] + part[512 + ix];
        }
        __syncthreads();
    }
}

extern "C" void kernel_launch(void* const* d_in, const int* in_sizes, int n_in,
                              void* d_out, int out_size)
{
    const float* x    = (const float*)d_in[0];
    const float* rbf  = (const float*)d_in[1];
    const int*   idxj = (const int*)  d_in[3];
    const float* k2f  = (const float*)d_in[4];
    const float* wi   = (const float*)d_in[5];
    const float* bi   = (const float*)d_in[6];
    const float* wj   = (const float*)d_in[7];
    const float* bj   = (const float*)d_in[8];
    const float* rw1  = (const float*)d_in[9];
    const float* rb1  = (const float*)d_in[10];
    const float* rw2  = (const float*)d_in[11];
    const float* rb2  = (const float*)d_in[12];
    const float* wd   = (const float*)d_in[13];
    const float* bd   = (const float*)d_in[14];
    const float* u    = (const float*)d_in[15];
    float* out = (float*)d_out;

    float *xi_p, *xjp_p, *m0_p, *m1_p, *t_p;
    cudaGetSymbolAddress((void**)&xi_p,  g_xi);
    cudaGetSymbolAddress((void**)&xjp_p, g_xjp);
    cudaGetSymbolAddress((void**)&m0_p,  g_m0);
    cudaGetSymbolAddress((void**)&m1_p,  g_m1);
    cudaGetSymbolAddress((void**)&t_p,   g_t);

    static int nsm = 0;
    if (nsm == 0) {
        cudaDeviceGetAttribute(&nsm, cudaDevAttrMultiProcessorCount, 0);
        if (nsm <= 0) nsm = 148;
        cudaFuncSetAttribute(attn_mma, cudaFuncAttributeMaxDynamicSharedMemorySize, SM_TOTAL);
    }

    const int GG = nsm * 3;

    rowgemm<true,  false, false><<<GG, 128>>>(x,    wi, bi, nullptr, nullptr, xi_p);
    rowgemm<true,  false, false><<<GG, 128>>>(x,    wj, bj, nullptr, nullptr, xjp_p);

    attn_mma<<<nsm, 256, SM_TOTAL>>>(rbf, idxj, k2f, xi_p, xjp_p, m0_p);

    rowgemm<true,  false, false><<<GG, 128>>>(m0_p, rw1,             rb1,        nullptr, nullptr, t_p);
    rowgemm<false, true,  false><<<GG, 128>>>(t_p,  rw2,             rb2,        m0_p,    nullptr, m1_p);
    rowgemm<true,  false, false><<<GG, 128>>>(m1_p, rw1 + FDIM*FDIM, rb1 + FDIM, nullptr, nullptr, t_p);
    rowgemm<false, true,  false><<<GG, 128>>>(t_p,  rw2 + FDIM*FDIM, rb2 + FDIM, m1_p,    nullptr, m0_p);
    rowgemm<true,  true,  true ><<<GG, 128>>>(m0_p, wd,              bd,         x,       u,       out);
}

// round 5
// speedup vs baseline: 2.0638x; 2.0638x over previous
#include <cuda_runtime.h>
#include <cuda_bf16.h>
#include <cstdint>
#include <math.h>

#define NROWS 32768
#define FDIM  128
#define KDIM  64
#define MNBR  32
#define NTILES (NROWS/4)

// Scratch (allocation-free rule: __device__ globals)
__device__ float g_xi [NROWS*FDIM];
__device__ float g_xjp[NROWS*FDIM];
__device__ float g_m0 [NROWS*FDIM];
__device__ float g_m1 [NROWS*FDIM];
__device__ float g_t  [NROWS*FDIM];

__device__ __forceinline__ float sspf(float a) {
    return fmaxf(a, 0.0f) + log1pf(expf(-fabsf(a))) - 0.69314718055994530942f;
}

// ---------------- row GEMM (unchanged, validated) ----------------
template<bool IN_SSP, bool ADD, bool MULVEC>
__global__ __launch_bounds__(128, 3) void rowgemm(
    const float* __restrict__ in, const float* __restrict__ W,
    const float* __restrict__ bias, const float* __restrict__ addp,
    const float* __restrict__ mulv, float* __restrict__ out)
{
    __shared__ float xs[8 * FDIM];
    const int f = threadIdx.x;

    float w[FDIM];
    {
        const float4* W4 = (const float4*)(W + f * FDIM);
        #pragma unroll
        for (int i = 0; i < FDIM / 4; i++) {
            float4 v = W4[i];
            w[4*i] = v.x; w[4*i+1] = v.y; w[4*i+2] = v.z; w[4*i+3] = v.w;
        }
    }
    const float bf = bias[f];
    const float mv = MULVEC ? mulv[f] : 1.0f;

    const int ntiles = NROWS / 8;
    for (int tile = blockIdx.x; tile < ntiles; tile += gridDim.x) {
        const int r0 = tile * 8;
        const float4* inp = (const float4*)(in + r0 * FDIM);
        float4* xs4 = (float4*)xs;
        #pragma unroll
        for (int i = 0; i < 2; i++) {
            float4 v = inp[f + 128 * i];
            if (IN_SSP) { v.x = sspf(v.x); v.y = sspf(v.y); v.z = sspf(v.z); v.w = sspf(v.w); }
            xs4[f + 128 * i] = v;
        }
        __syncthreads();
        for (int r = 0; r < 8; r++) {
            const float4* xr = (const float4*)(xs + r * FDIM);
            float a0 = 0.f, a1 = 0.f, a2 = 0.f, a3 = 0.f;
            #pragma unroll
            for (int kk = 0; kk < FDIM / 4; kk++) {
                float4 v = xr[kk];
                a0 += v.x * w[4*kk];   a1 += v.y * w[4*kk+1];
                a2 += v.z * w[4*kk+2]; a3 += v.w * w[4*kk+3];
            }
            float o = bf + ((a0 + a1) + (a2 + a3));
            const int n = r0 + r;
            if (ADD) o += addp[n * FDIM + f] * mv;
            out[n * FDIM + f] = o;
        }
        __syncthreads();
    }
}

// ---------------- mma.sync helpers ----------------
__device__ __forceinline__ uint32_t s2u(const void* p) {
    uint32_t a;
    asm("{ .reg .u64 t; cvta.to.shared.u64 t, %1; cvt.u32.u64 %0, t; }" : "=r"(a) : "l"(p));
    return a;
}

#define LDM_X4(r, addr) \
    asm volatile("ldmatrix.sync.aligned.m8n8.x4.shared.b16 {%0,%1,%2,%3}, [%4];" \
        : "=r"((r)[0]), "=r"((r)[1]), "=r"((r)[2]), "=r"((r)[3]) : "r"(addr))

#define MMA_BF16(d, a, b0, b1) \
    asm volatile("mma.sync.aligned.m16n8k16.row.col.f32.bf16.bf16.f32 " \
        "{%0,%1,%2,%3}, {%4,%5,%6,%7}, {%8,%9}, {%0,%1,%2,%3};" \
        : "+f"((d)[0]), "+f"((d)[1]), "+f"((d)[2]), "+f"((d)[3]) \
        : "r"((a)[0]), "r"((a)[1]), "r"((a)[2]), "r"((a)[3]), "r"(b0), "r"(b1))

// ---------------- smem layout (bytes) ----------------
// bf16 tiles: [row][72] (pad 8) -> 144 B/row. Slab UNION with A region (A dead after MMA).
#define OFF_BH   0u
#define OFF_BL   18432u
#define OFF_U    36864u          // AH here; AL at +18432; slab (float[128][132]=67584B) also here
#define OFF_AH   OFF_U
#define OFF_AL   (OFF_U + 18432u)
#define OFF_XI   104448u         // float[512]
#define OFF_PART 106496u         // float[2048]
#define OFF_ATT  114688u         // float[128]
#define OFF_JIDX 115200u         // int[128]
#define SM_TOTAL 115712u

#define SLAB_STRIDE 132

__global__ void nopk() {}

// ---------------- fused edge-filter GEMM (mma.sync bf16x3) + gather + attention ----------------
__global__ void __launch_bounds__(512, 1) attn_mma(
    const float* __restrict__ rbf, const int* __restrict__ idxj,
    const float* __restrict__ k2f, const float* __restrict__ xi,
    const float* __restrict__ xjp, float* __restrict__ mout)
{
    extern __shared__ char smem[];
    __nv_bfloat16* AH = (__nv_bfloat16*)(smem + OFF_AH);
    __nv_bfloat16* AL = (__nv_bfloat16*)(smem + OFF_AL);
    __nv_bfloat16* BH = (__nv_bfloat16*)(smem + OFF_BH);
    __nv_bfloat16* BL = (__nv_bfloat16*)(smem + OFF_BL);
    float* slab   = (float*)(smem + OFF_U);
    float* xi_sm  = (float*)(smem + OFF_XI);
    float* part   = (float*)(smem + OFF_PART);
    float* att_sm = (float*)(smem + OFF_ATT);
    int*   jidx   = (int*)  (smem + OFF_JIDX);

    const int tid = threadIdx.x;
    const int wid = tid >> 5, lid = tid & 31;
    const uint32_t sb = s2u(smem);

    // B = k2f [128 f x 64 k], hi/lo bf16 split, loaded once
    #pragma unroll
    for (int i = 0; i < 4; i++) {
        int fidx = tid + 512 * i;             // float4 index, 2048 total
        float4 v = ((const float4*)k2f)[fidx];
        int row = fidx >> 4, c = (fidx & 15) * 4;
        __nv_bfloat16 h0 = __float2bfloat16(v.x), h1 = __float2bfloat16(v.y),
                      h2 = __float2bfloat16(v.z), h3 = __float2bfloat16(v.w);
        __nv_bfloat16 l0 = __float2bfloat16(v.x - __bfloat162float(h0)),
                      l1 = __float2bfloat16(v.y - __bfloat162float(h1)),
                      l2 = __float2bfloat16(v.z - __bfloat162float(h2)),
                      l3 = __float2bfloat16(v.w - __bfloat162float(h3));
        *(__nv_bfloat162*)(BH + row*72 + c)     = __nv_bfloat162(h0, h1);
        *(__nv_bfloat162*)(BH + row*72 + c + 2) = __nv_bfloat162(h2, h3);
        *(__nv_bfloat162*)(BL + row*72 + c)     = __nv_bfloat162(l0, l1);
        *(__nv_bfloat162*)(BL + row*72 + c + 2) = __nv_bfloat162(l2, l3);
    }
    __syncthreads();

    // per-lane ldmatrix byte offsets (validated mapping from R3)
    const uint32_t aL = ((((lid & 7) + (lid & 8)) * 72) + ((lid & 16) ? 8 : 0)) * 2;
    const uint32_t bL = ((((lid & 7) + ((lid & 16) >> 1)) * 72) + ((lid & 8) ? 8 : 0)) * 2;
    const int wr = wid & 3, wc = wid >> 2;   // warp tile: 32 edges x 32 cols

    const int f  = tid & 127;
    const int q  = f >> 5;
    const int e0 = tid >> 7;                 // 0..3

    for (int tile = blockIdx.x; tile < NTILES; tile += gridDim.x) {
        const int n0 = tile * 4;

        // A tile: 128 edges x 64 rbf, hi/lo split (into union region)
        const float4* rp = (const float4*)(rbf + (size_t)tile * 8192);
        #pragma unroll
        for (int i = 0; i < 4; i++) {
            int fidx = tid + 512 * i;
            float4 v = rp[fidx];
            int row = fidx >> 4, c = (fidx & 15) * 4;
            __nv_bfloat16 h0 = __float2bfloat16(v.x), h1 = __float2bfloat16(v.y),
                          h2 = __float2bfloat16(v.z), h3 = __float2bfloat16(v.w);
            __nv_bfloat16 l0 = __float2bfloat16(v.x - __bfloat162float(h0)),
                          l1 = __float2bfloat16(v.y - __bfloat162float(h1)),
                          l2 = __float2bfloat16(v.z - __bfloat162float(h2)),
                          l3 = __float2bfloat16(v.w - __bfloat162float(h3));
            *(__nv_bfloat162*)(AH + row*72 + c)     = __nv_bfloat162(h0, h1);
            *(__nv_bfloat162*)(AH + row*72 + c + 2) = __nv_bfloat162(h2, h3);
            *(__nv_bfloat162*)(AL + row*72 + c)     = __nv_bfloat162(l0, l1);
            *(__nv_bfloat162*)(AL + row*72 + c + 2) = __nv_bfloat162(l2, l3);
        }
        if (tid < 128) jidx[tid] = idxj[tile * 128 + tid];
        if (tid < 512) xi_sm[tid] = xi[(size_t)n0 * FDIM + tid];
        __syncthreads();

        // 128x128x64 GEMM: D[e][f] = sum_k A[e][k]*B[f][k], bf16 hi/lo 3-pass
        float acc[2][4][4];
        #pragma unroll
        for (int mt = 0; mt < 2; mt++)
            #pragma unroll
            for (int nb = 0; nb < 4; nb++)
                #pragma unroll
                for (int c = 0; c < 4; c++) acc[mt][nb][c] = 0.f;

        #pragma unroll
        for (int kk = 0; kk < 4; kk++) {
            const uint32_t kb = (uint32_t)kk * 32;
            uint32_t ah[2][4], al[2][4], bh[2][4], bl[2][4];
            #pragma unroll
            for (int mt = 0; mt < 2; mt++) {
                uint32_t ro = (uint32_t)(32*wr + 16*mt) * 144 + kb;
                LDM_X4(ah[mt], sb + OFF_AH + aL + ro);
                LDM_X4(al[mt], sb + OFF_AL + aL + ro);
            }
            #pragma unroll
            for (int np = 0; np < 2; np++) {
                uint32_t no = (uint32_t)(32*wc + 16*np) * 144 + kb;
                LDM_X4(bh[np], sb + OFF_BH + bL + no);
                LDM_X4(bl[np], sb + OFF_BL + bL + no);
            }
            #pragma unroll
            for (int mt = 0; mt < 2; mt++)
                #pragma unroll
                for (int np = 0; np < 2; np++) {
                    MMA_BF16(acc[mt][2*np],   ah[mt], bh[np][0], bh[np][1]);
                    MMA_BF16(acc[mt][2*np+1], ah[mt], bh[np][2], bh[np][3]);
                    MMA_BF16(acc[mt][2*np],   ah[mt], bl[np][0], bl[np][1]);
                    MMA_BF16(acc[mt][2*np+1], ah[mt], bl[np][2], bl[np][3]);
                    MMA_BF16(acc[mt][2*np],   al[mt], bh[np][0], bh[np][1]);
                    MMA_BF16(acc[mt][2*np+1], al[mt], bh[np][2], bh[np][3]);
                }
        }
        __syncthreads();   // all MMA reads of A done -> safe to overwrite union with slab

        // fragment -> slab  (lane l: rows g,g+8; cols 2t,2t+1)
        {
            const int g = lid >> 2, t = lid & 3;
            #pragma unroll
            for (int mt = 0; mt < 2; mt++)
                #pragma unroll
                for (int nb = 0; nb < 4; nb++) {
                    int e = 32*wr + 16*mt + g;
                    int c = 32*wc + 8*nb + 2*t;
                    *(float2*)&slab[e * SLAB_STRIDE + c] =
                        make_float2(acc[mt][nb][0], acc[mt][nb][1]);
                    *(float2*)&slab[(e + 8) * SLAB_STRIDE + c] =
                        make_float2(acc[mt][nb][2], acc[mt][nb][3]);
                }
        }
        __syncthreads();

        // gather batch: 32 independent LDGs per thread (front-batched -> high MLP)
        float xp[32];
        #pragma unroll
        for (int i = 0; i < 32; i++)
            xp[i] = xjp[(size_t)jidx[4*i + e0] * FDIM + f];

        // product + logit partials (faithful flat reshape: slot (a, f&31))
        float lacc[4] = {0.f, 0.f, 0.f, 0.f};
        #pragma unroll
        for (int i = 0; i < 32; i++) {
            const int e = 4*i + e0;
            const int a = i >> 3;            // compile-time per unrolled i
            const int m = e & 31;
            float p = slab[e * SLAB_STRIDE + f] * xp[i];
            xp[i] = p;
            lacc[a] += xi_sm[a * FDIM + 4*m + q] * p;
        }
        #pragma unroll
        for (int a = 0; a < 4; a++)
            part[wid * 128 + a * 32 + lid] = lacc[a];
        __syncthreads();

        if (wid < 4) {
            float lg = 0.f;
            #pragma unroll
            for (int w2 = 0; w2 < 16; w2++) lg += part[w2 * 128 + wid * 32 + lid];
            float mx = lg;
            #pragma unroll
            for (int o = 16; o; o >>= 1) mx = fmaxf(mx, __shfl_xor_sync(0xffffffffu, mx, o));
            float ex = expf(lg - mx);
            float smv = ex;
            #pragma unroll
            for (int o = 16; o; o >>= 1) smv += __shfl_xor_sync(0xffffffffu, smv, o);
            att_sm[wid * 32 + lid] = ex / smv;
        }
        __syncthreads();

        // attention-weighted neighbor sum from product registers
        float pacc[4] = {0.f, 0.f, 0.f, 0.f};
        #pragma unroll
        for (int i = 0; i < 32; i++) {
            const int e = 4*i + e0;
            const int a = i >> 3;
            const int m = e & 31;
            pacc[a] += att_sm[a * 32 + m] * xp[i];
        }
        #pragma unroll
        for (int a = 0; a < 4; a++)
            part[e0 * 512 + a * 128 + f] = pacc[a];
        __syncthreads();

        mout[(size_t)n0 * FDIM + tid] = xi_sm[tid]
            + part[tid] + part[512 + tid] + part[1024 + tid] + part[1536 + tid];
        __syncthreads();
    }
}

extern "C" void kernel_launch(void* const* d_in, const int* in_sizes, int n_in,
                              void* d_out, int out_size)
{
    const float* x    = (const float*)d_in[0];
    const float* rbf  = (const float*)d_in[1];
    const int*   idxj = (const int*)  d_in[3];
    const float* k2f  = (const float*)d_in[4];
    const float* wi   = (const float*)d_in[5];
    const float* bi   = (const float*)d_in[6];
    const float* wj   = (const float*)d_in[7];
    const float* bj   = (const float*)d_in[8];
    const float* rw1  = (const float*)d_in[9];
    const float* rb1  = (const float*)d_in[10];
    const float* rw2  = (const float*)d_in[11];
    const float* rb2  = (const float*)d_in[12];
    const float* wd   = (const float*)d_in[13];
    const float* bd   = (const float*)d_in[14];
    const float* u    = (const float*)d_in[15];
    float* out = (float*)d_out;

    float *xi_p, *xjp_p, *m0_p, *m1_p, *t_p;
    cudaGetSymbolAddress((void**)&xi_p,  g_xi);
    cudaGetSymbolAddress((void**)&xjp_p, g_xjp);
    cudaGetSymbolAddress((void**)&m0_p,  g_m0);
    cudaGetSymbolAddress((void**)&m1_p,  g_m1);
    cudaGetSymbolAddress((void**)&t_p,   g_t);

    static int nsm = 0;
    if (nsm == 0) {
        cudaDeviceGetAttribute(&nsm, cudaDevAttrMultiProcessorCount, 0);
        if (nsm <= 0) nsm = 148;
        cudaFuncSetAttribute(attn_mma, cudaFuncAttributeMaxDynamicSharedMemorySize, SM_TOTAL);
    }

    const int GG = nsm * 3;

    rowgemm<true,  false, false><<<GG, 128>>>(x,    wi, bi, nullptr, nullptr, xi_p);   // launch 0
    rowgemm<true,  false, false><<<GG, 128>>>(x,    wj, bj, nullptr, nullptr, xjp_p);  // launch 1

    // padding so ncu (-s 5 -c 1) captures attn_mma as launch index 5
    nopk<<<1, 32>>>();                                                                 // launch 2
    nopk<<<1, 32>>>();                                                                 // launch 3
    nopk<<<1, 32>>>();                                                                 // launch 4

    attn_mma<<<nsm, 512, SM_TOTAL>>>(rbf, idxj, k2f, xi_p, xjp_p, m0_p);               // launch 5

    rowgemm<true,  false, false><<<GG, 128>>>(m0_p, rw1,             rb1,        nullptr, nullptr, t_p);
    rowgemm<false, true,  false><<<GG, 128>>>(t_p,  rw2,             rb2,        m0_p,    nullptr, m1_p);
    rowgemm<true,  false, false><<<GG, 128>>>(m1_p, rw1 + FDIM*FDIM, rb1 + FDIM, nullptr, nullptr, t_p);
    rowgemm<false, true,  false><<<GG, 128>>>(t_p,  rw2 + FDIM*FDIM, rb2 + FDIM, m1_p,    nullptr, m0_p);
    rowgemm<true,  true,  true ><<<GG, 128>>>(m0_p, wd,              bd,         x,       u,       out);
}

// round 6
// speedup vs baseline: 2.8942x; 1.4024x over previous
#include <cuda_runtime.h>
#include <cuda_bf16.h>
#include <cstdint>
#include <math.h>

#define NROWS 32768
#define FDIM  128
#define KDIM  64
#define MNBR  32
#define NTILES (NROWS/4)

// Scratch (allocation-free rule: __device__ globals)
__device__ float g_xi [NROWS*FDIM];
__device__ float g_xjp[NROWS*FDIM];
__device__ float g_m0 [NROWS*FDIM];
__device__ float g_m1 [NROWS*FDIM];
__device__ float g_t  [NROWS*FDIM];

__device__ __forceinline__ float sspf(float a) {
    return fmaxf(a, 0.0f) + log1pf(expf(-fabsf(a))) - 0.69314718055994530942f;
}

// ---------------- mma.sync helpers ----------------
__device__ __forceinline__ uint32_t s2u(const void* p) {
    uint32_t a;
    asm("{ .reg .u64 t; cvta.to.shared.u64 t, %1; cvt.u32.u64 %0, t; }" : "=r"(a) : "l"(p));
    return a;
}

#define LDM_X4(r, addr) \
    asm volatile("ldmatrix.sync.aligned.m8n8.x4.shared.b16 {%0,%1,%2,%3}, [%4];" \
        : "=r"((r)[0]), "=r"((r)[1]), "=r"((r)[2]), "=r"((r)[3]) : "r"(addr))

#define MMA_BF16(d, a, b0, b1) \
    asm volatile("mma.sync.aligned.m16n8k16.row.col.f32.bf16.bf16.f32 " \
        "{%0,%1,%2,%3}, {%4,%5,%6,%7}, {%8,%9}, {%0,%1,%2,%3};" \
        : "+f"((d)[0]), "+f"((d)[1]), "+f"((d)[2]), "+f"((d)[3]) \
        : "r"((a)[0]), "r"((a)[1]), "r"((a)[2]), "r"((a)[3]), "r"(b0), "r"(b1))

__device__ __forceinline__ void bf16_split4(float4 v, __nv_bfloat16* H, __nv_bfloat16* L) {
    __nv_bfloat16 h0 = __float2bfloat16(v.x), h1 = __float2bfloat16(v.y),
                  h2 = __float2bfloat16(v.z), h3 = __float2bfloat16(v.w);
    *(__nv_bfloat162*)(H)     = __nv_bfloat162(h0, h1);
    *(__nv_bfloat162*)(H + 2) = __nv_bfloat162(h2, h3);
    *(__nv_bfloat162*)(L)     = __nv_bfloat162(__float2bfloat16(v.x - __bfloat162float(h0)),
                                               __float2bfloat16(v.y - __bfloat162float(h1)));
    *(__nv_bfloat162*)(L + 2) = __nv_bfloat162(__float2bfloat16(v.z - __bfloat162float(h2)),
                                               __float2bfloat16(v.w - __bfloat162float(h3)));
}

// =================================================================================
// Tensor-core row GEMM: out[n,f] = epi( sum_k act(in[n,k]) * W[f,k] + b[f] )
// 512 threads, one 128x128 output tile per CTA. bf16 hi/lo 3-pass mma.sync.
// =================================================================================
// smem (bytes): W rows padded to 136 bf16 (272B)
#define TG_WH    0u
#define TG_WL    34816u
#define TG_A     69632u            // AH; AL at +34816; fp32 slab[128][132] unions here
#define TG_AH    TG_A
#define TG_AL    (TG_A + 34816u)
#define TG_BIAS  139264u           // float[128]
#define TG_MUL   139776u           // float[128]
#define TG_TOTAL 140288u
#define TG_SLABS 132

template<bool IN_SSP, bool ADD, bool MULVEC>
__global__ __launch_bounds__(512, 1) void trowgemm(
    const float* __restrict__ in, const float* __restrict__ W,
    const float* __restrict__ bias, const float* __restrict__ addp,
    const float* __restrict__ mulv, float* __restrict__ out)
{
    extern __shared__ char smem[];
    __nv_bfloat16* WH = (__nv_bfloat16*)(smem + TG_WH);
    __nv_bfloat16* WL = (__nv_bfloat16*)(smem + TG_WL);
    __nv_bfloat16* AH = (__nv_bfloat16*)(smem + TG_AH);
    __nv_bfloat16* AL = (__nv_bfloat16*)(smem + TG_AL);
    float* slab = (float*)(smem + TG_A);
    float* b_sm = (float*)(smem + TG_BIAS);
    float* u_sm = (float*)(smem + TG_MUL);

    const int tid = threadIdx.x;
    const int wid = tid >> 5, lid = tid & 31;
    const uint32_t sb = s2u(smem);

    // weights: 128x128 fp32 -> hi/lo bf16 [row][136]
    #pragma unroll
    for (int i = 0; i < 8; i++) {
        int fidx = tid + 512 * i;            // float4 idx over 4096
        float4 v = ((const float4*)W)[fidx];
        int row = fidx >> 5, c = (fidx & 31) * 4;
        bf16_split4(v, WH + row * 136 + c, WL + row * 136 + c);
    }
    if (tid < 128) {
        b_sm[tid] = bias[tid];
        u_sm[tid] = MULVEC ? mulv[tid] : 0.0f;
    }

    const int r0 = blockIdx.x * 128;

    // input tile: act + split
    #pragma unroll
    for (int i = 0; i < 8; i++) {
        int fidx = tid + 512 * i;
        float4 v = ((const float4*)(in + (size_t)r0 * FDIM))[fidx];
        if (IN_SSP) { v.x = sspf(v.x); v.y = sspf(v.y); v.z = sspf(v.z); v.w = sspf(v.w); }
        int row = fidx >> 5, c = (fidx & 31) * 4;
        bf16_split4(v, AH + row * 136 + c, AL + row * 136 + c);
    }
    __syncthreads();

    // per-lane ldmatrix byte offsets (stride 136 bf16 = 272 B)
    const uint32_t aL = (((lid & 7) + (lid & 8)) * 136 + ((lid & 16) ? 8 : 0)) * 2;
    const uint32_t bL = (((lid & 7) + ((lid & 16) >> 1)) * 136 + ((lid & 8) ? 8 : 0)) * 2;
    const int wr = wid & 3, wc = wid >> 2;   // warp: 32 rows x 32 cols

    float acc[2][4][4];
    #pragma unroll
    for (int mt = 0; mt < 2; mt++)
        #pragma unroll
        for (int nb = 0; nb < 4; nb++)
            #pragma unroll
            for (int c = 0; c < 4; c++) acc[mt][nb][c] = 0.f;

    #pragma unroll
    for (int kk = 0; kk < 8; kk++) {
        const uint32_t kb = (uint32_t)kk * 32;
        uint32_t ah[2][4], al[2][4], bh[2][4], bl[2][4];
        #pragma unroll
        for (int mt = 0; mt < 2; mt++) {
            uint32_t ro = (uint32_t)(32*wr + 16*mt) * 272 + kb;
            LDM_X4(ah[mt], sb + TG_AH + aL + ro);
            LDM_X4(al[mt], sb + TG_AL + aL + ro);
        }
        #pragma unroll
        for (int np = 0; np < 2; np++) {
            uint32_t no = (uint32_t)(32*wc + 16*np) * 272 + kb;
            LDM_X4(bh[np], sb + TG_WH + bL + no);
            LDM_X4(bl[np], sb + TG_WL + bL + no);
        }
        #pragma unroll
        for (int mt = 0; mt < 2; mt++)
            #pragma unroll
            for (int np = 0; np < 2; np++) {
                MMA_BF16(acc[mt][2*np],   ah[mt], bh[np][0], bh[np][1]);
                MMA_BF16(acc[mt][2*np+1], ah[mt], bh[np][2], bh[np][3]);
                MMA_BF16(acc[mt][2*np],   ah[mt], bl[np][0], bl[np][1]);
                MMA_BF16(acc[mt][2*np+1], ah[mt], bl[np][2], bl[np][3]);
                MMA_BF16(acc[mt][2*np],   al[mt], bh[np][0], bh[np][1]);
                MMA_BF16(acc[mt][2*np+1], al[mt], bh[np][2], bh[np][3]);
            }
    }
    __syncthreads();   // A reads done -> union region becomes slab

    {
        const int g = lid >> 2, t = lid & 3;
        #pragma unroll
        for (int mt = 0; mt < 2; mt++)
            #pragma unroll
            for (int nb = 0; nb < 4; nb++) {
                int e = 32*wr + 16*mt + g;
                int c = 32*wc + 8*nb + 2*t;
                *(float2*)&slab[e * TG_SLABS + c] = make_float2(acc[mt][nb][0], acc[mt][nb][1]);
                *(float2*)&slab[(e+8) * TG_SLABS + c] = make_float2(acc[mt][nb][2], acc[mt][nb][3]);
            }
    }
    __syncthreads();

    // coalesced epilogue
    #pragma unroll
    for (int i = 0; i < 32; i++) {
        int idx = tid + 512 * i;
        int row = idx >> 7, col = idx & 127;
        float o = slab[row * TG_SLABS + col] + b_sm[col];
        if (ADD) {
            float av = addp[(size_t)(r0 + row) * FDIM + col];
            o += MULVEC ? av * u_sm[col] : av;
        }
        out[(size_t)(r0 + row) * FDIM + col] = o;
    }
}

// =================================================================================
// Fused edge-filter GEMM (mma.sync bf16x3) + gather + attention  (validated R4)
// =================================================================================
#define OFF_BH   0u
#define OFF_BL   18432u
#define OFF_U    36864u
#define OFF_AH   OFF_U
#define OFF_AL   (OFF_U + 18432u)
#define OFF_XI   104448u
#define OFF_PART 106496u
#define OFF_ATT  114688u
#define OFF_JIDX 115200u
#define SM_TOTAL 115712u
#define SLAB_STRIDE 132

__global__ void __launch_bounds__(512, 1) attn_mma(
    const float* __restrict__ rbf, const int* __restrict__ idxj,
    const float* __restrict__ k2f, const float* __restrict__ xi,
    const float* __restrict__ xjp, float* __restrict__ mout)
{
    extern __shared__ char smem[];
    __nv_bfloat16* AH = (__nv_bfloat16*)(smem + OFF_AH);
    __nv_bfloat16* AL = (__nv_bfloat16*)(smem + OFF_AL);
    __nv_bfloat16* BH = (__nv_bfloat16*)(smem + OFF_BH);
    __nv_bfloat16* BL = (__nv_bfloat16*)(smem + OFF_BL);
    float* slab   = (float*)(smem + OFF_U);
    float* xi_sm  = (float*)(smem + OFF_XI);
    float* part   = (float*)(smem + OFF_PART);
    float* att_sm = (float*)(smem + OFF_ATT);
    int*   jidx   = (int*)  (smem + OFF_JIDX);

    const int tid = threadIdx.x;
    const int wid = tid >> 5, lid = tid & 31;
    const uint32_t sb = s2u(smem);

    #pragma unroll
    for (int i = 0; i < 4; i++) {
        int fidx = tid + 512 * i;
        float4 v = ((const float4*)k2f)[fidx];
        int row = fidx >> 4, c = (fidx & 15) * 4;
        bf16_split4(v, BH + row*72 + c, BL + row*72 + c);
    }
    __syncthreads();

    const uint32_t aL = ((((lid & 7) + (lid & 8)) * 72) + ((lid & 16) ? 8 : 0)) * 2;
    const uint32_t bL = ((((lid & 7) + ((lid & 16) >> 1)) * 72) + ((lid & 8) ? 8 : 0)) * 2;
    const int wr = wid & 3, wc = wid >> 2;

    const int f  = tid & 127;
    const int q  = f >> 5;
    const int e0 = tid >> 7;

    for (int tile = blockIdx.x; tile < NTILES; tile += gridDim.x) {
        const int n0 = tile * 4;

        const float4* rp = (const float4*)(rbf + (size_t)tile * 8192);
        #pragma unroll
        for (int i = 0; i < 4; i++) {
            int fidx = tid + 512 * i;
            float4 v = rp[fidx];
            int row = fidx >> 4, c = (fidx & 15) * 4;
            bf16_split4(v, AH + row*72 + c, AL + row*72 + c);
        }
        if (tid < 128) jidx[tid] = idxj[tile * 128 + tid];
        if (tid < 512) xi_sm[tid] = xi[(size_t)n0 * FDIM + tid];
        __syncthreads();

        float acc[2][4][4];
        #pragma unroll
        for (int mt = 0; mt < 2; mt++)
            #pragma unroll
            for (int nb = 0; nb < 4; nb++)
                #pragma unroll
                for (int c = 0; c < 4; c++) acc[mt][nb][c] = 0.f;

        #pragma unroll
        for (int kk = 0; kk < 4; kk++) {
            const uint32_t kb = (uint32_t)kk * 32;
            uint32_t ah[2][4], al[2][4], bh[2][4], bl[2][4];
            #pragma unroll
            for (int mt = 0; mt < 2; mt++) {
                uint32_t ro = (uint32_t)(32*wr + 16*mt) * 144 + kb;
                LDM_X4(ah[mt], sb + OFF_AH + aL + ro);
                LDM_X4(al[mt], sb + OFF_AL + aL + ro);
            }
            #pragma unroll
            for (int np = 0; np < 2; np++) {
                uint32_t no = (uint32_t)(32*wc + 16*np) * 144 + kb;
                LDM_X4(bh[np], sb + OFF_BH + bL + no);
                LDM_X4(bl[np], sb + OFF_BL + bL + no);
            }
            #pragma unroll
            for (int mt = 0; mt < 2; mt++)
                #pragma unroll
                for (int np = 0; np < 2; np++) {
                    MMA_BF16(acc[mt][2*np],   ah[mt], bh[np][0], bh[np][1]);
                    MMA_BF16(acc[mt][2*np+1], ah[mt], bh[np][2], bh[np][3]);
                    MMA_BF16(acc[mt][2*np],   ah[mt], bl[np][0], bl[np][1]);
                    MMA_BF16(acc[mt][2*np+1], ah[mt], bl[np][2], bl[np][3]);
                    MMA_BF16(acc[mt][2*np],   al[mt], bh[np][0], bh[np][1]);
                    MMA_BF16(acc[mt][2*np+1], al[mt], bh[np][2], bh[np][3]);
                }
        }
        __syncthreads();

        {
            const int g = lid >> 2, t = lid & 3;
            #pragma unroll
            for (int mt = 0; mt < 2; mt++)
                #pragma unroll
                for (int nb = 0; nb < 4; nb++) {
                    int e = 32*wr + 16*mt + g;
                    int c = 32*wc + 8*nb + 2*t;
                    *(float2*)&slab[e * SLAB_STRIDE + c] =
                        make_float2(acc[mt][nb][0], acc[mt][nb][1]);
                    *(float2*)&slab[(e + 8) * SLAB_STRIDE + c] =
                        make_float2(acc[mt][nb][2], acc[mt][nb][3]);
                }
        }
        __syncthreads();

        float xp[32];
        #pragma unroll
        for (int i = 0; i < 32; i++)
            xp[i] = xjp[(size_t)jidx[4*i + e0] * FDIM + f];

        float lacc[4] = {0.f, 0.f, 0.f, 0.f};
        #pragma unroll
        for (int i = 0; i < 32; i++) {
            const int e = 4*i + e0;
            const int a = i >> 3;
            const int m = e & 31;
            float p = slab[e * SLAB_STRIDE + f] * xp[i];
            xp[i] = p;
            lacc[a] += xi_sm[a * FDIM + 4*m + q] * p;
        }
        #pragma unroll
        for (int a = 0; a < 4; a++)
            part[wid * 128 + a * 32 + lid] = lacc[a];
        __syncthreads();

        if (wid < 4) {
            float lg = 0.f;
            #pragma unroll
            for (int w2 = 0; w2 < 16; w2++) lg += part[w2 * 128 + wid * 32 + lid];
            float mx = lg;
            #pragma unroll
            for (int o = 16; o; o >>= 1) mx = fmaxf(mx, __shfl_xor_sync(0xffffffffu, mx, o));
            float ex = expf(lg - mx);
            float smv = ex;
            #pragma unroll
            for (int o = 16; o; o >>= 1) smv += __shfl_xor_sync(0xffffffffu, smv, o);
            att_sm[wid * 32 + lid] = ex / smv;
        }
        __syncthreads();

        float pacc[4] = {0.f, 0.f, 0.f, 0.f};
        #pragma unroll
        for (int i = 0; i < 32; i++) {
            const int e = 4*i + e0;
            const int a = i >> 3;
            const int m = e & 31;
            pacc[a] += att_sm[a * 32 + m] * xp[i];
        }
        #pragma unroll
        for (int a = 0; a < 4; a++)
            part[e0 * 512 + a * 128 + f] = pacc[a];
        __syncthreads();

        mout[(size_t)n0 * FDIM + tid] = xi_sm[tid]
            + part[tid] + part[512 + tid] + part[1024 + tid] + part[1536 + tid];
        __syncthreads();
    }
}

extern "C" void kernel_launch(void* const* d_in, const int* in_sizes, int n_in,
                              void* d_out, int out_size)
{
    const float* x    = (const float*)d_in[0];
    const float* rbf  = (const float*)d_in[1];
    const int*   idxj = (const int*)  d_in[3];
    const float* k2f  = (const float*)d_in[4];
    const float* wi   = (const float*)d_in[5];
    const float* bi   = (const float*)d_in[6];
    const float* wj   = (const float*)d_in[7];
    const float* bj   = (const float*)d_in[8];
    const float* rw1  = (const float*)d_in[9];
    const float* rb1  = (const float*)d_in[10];
    const float* rw2  = (const float*)d_in[11];
    const float* rb2  = (const float*)d_in[12];
    const float* wd   = (const float*)d_in[13];
    const float* bd   = (const float*)d_in[14];
    const float* u    = (const float*)d_in[15];
    float* out = (float*)d_out;

    float *xi_p, *xjp_p, *m0_p, *m1_p, *t_p;
    cudaGetSymbolAddress((void**)&xi_p,  g_xi);
    cudaGetSymbolAddress((void**)&xjp_p, g_xjp);
    cudaGetSymbolAddress((void**)&m0_p,  g_m0);
    cudaGetSymbolAddress((void**)&m1_p,  g_m1);
    cudaGetSymbolAddress((void**)&t_p,   g_t);

    static int nsm = 0;
    if (nsm == 0) {
        cudaDeviceGetAttribute(&nsm, cudaDevAttrMultiProcessorCount, 0);
        if (nsm <= 0) nsm = 148;
        cudaFuncSetAttribute(attn_mma, cudaFuncAttributeMaxDynamicSharedMemorySize, SM_TOTAL);
        cudaFuncSetAttribute(trowgemm<true,  false, false>, cudaFuncAttributeMaxDynamicSharedMemorySize, TG_TOTAL);
        cudaFuncSetAttribute(trowgemm<false, true,  false>, cudaFuncAttributeMaxDynamicSharedMemorySize, TG_TOTAL);
        cudaFuncSetAttribute(trowgemm<true,  true,  true >, cudaFuncAttributeMaxDynamicSharedMemorySize, TG_TOTAL);
    }

    const int TG_GRID = NROWS / 128;   // 256

    trowgemm<true,  false, false><<<TG_GRID, 512, TG_TOTAL>>>(x,    wi, bi, nullptr, nullptr, xi_p);
    trowgemm<true,  false, false><<<TG_GRID, 512, TG_TOTAL>>>(x,    wj, bj, nullptr, nullptr, xjp_p);

    attn_mma<<<nsm, 512, SM_TOTAL>>>(rbf, idxj, k2f, xi_p, xjp_p, m0_p);

    trowgemm<true,  false, false><<<TG_GRID, 512, TG_TOTAL>>>(m0_p, rw1,             rb1,        nullptr, nullptr, t_p);
    trowgemm<false, true,  false><<<TG_GRID, 512, TG_TOTAL>>>(t_p,  rw2,             rb2,        m0_p,    nullptr, m1_p);
    trowgemm<true,  false, false><<<TG_GRID, 512, TG_TOTAL>>>(m1_p, rw1 + FDIM*FDIM, rb1 + FDIM, nullptr, nullptr, t_p);
    trowgemm<false, true,  false><<<TG_GRID, 512, TG_TOTAL>>>(t_p,  rw2 + FDIM*FDIM, rb2 + FDIM, m1_p,    nullptr, m0_p);
    trowgemm<true,  true,  true ><<<TG_GRID, 512, TG_TOTAL>>>(m0_p, wd,              bd,         x,       u,       out);
}